// round 16
// baseline (speedup 1.0000x reference)
#include <cuda_runtime.h>

// RoiPooling: crop_and_resize(img[0], 2048 boxes, crop=7) over 512 channels.
// CTA = box, 128 threads = 512 channels as float4.
// Raw 2-row patch register cache (pT/pB, rows advance <= 1 per output row).
// Fused 6-tap outputs directly on the raw patch (no ry transient).
// 3-tap x-window weights in REGISTERS (21) — with ry gone this fits under the
// 128-reg cap with no spills and no smem: L1tex work is the bare minimum
// (36 LDG.128 + 49 STG.128 per box, zero LDS, zero LDL/STL).

#define IMG_H 28
#define IMG_W 28
#define C4    128          // 512 channels / 4
#define POOLN 7
#define NBOX  2048
#define ROWSTRIDE (IMG_W * C4)   // float4 elems per image row

#define LOADROW(rowc, dst) do {                                               \
    const float4* rp_ = base_img + (rowc) * ROWSTRIDE;                        \
    _Pragma("unroll")                                                         \
    for (int k_ = 0; k_ < 6; k_++) (dst)[k_] = __ldg(rp_ + colofs[k_]);       \
} while (0)

__global__ __launch_bounds__(128, 4) void roi_pool_kernel(
    const float4* __restrict__ img4,   // img[0] as float4: (28*28, 128)
    const float*  __restrict__ rois,
    float4* __restrict__ out4)
{
    // floor(j * 27*4/(28*6)) for j=0..6; j*sx stays >=0.07 from any integer,
    // far beyond f32 rounding wiggle, so ax[j]-ax[0] ∈ {BASE, BASE+1}.
    const int BASE_X[POOLN] = {0, 0, 1, 1, 2, 3, 3};

    const int box = blockIdx.x;
    const int tid = threadIdx.x;           // channel-quad 0..127

    const float x1 = rois[box * 5 + 3];
    const float y1 = rois[box * 5 + 4];
    const float win = (float)(4.0 / 28.0);
    // Match JAX numerics: ((x1+win)-x1)*27/6 in f32
    const float sx = (((x1 + win) - x1) * 27.0f) / 6.0f;
    const float sy = (((y1 + win) - y1) * 27.0f) / 6.0f;
    const float fx = x1 * 27.0f;
    const float fy = y1 * 27.0f;

    const int x_lo = (int)floorf(fx);      // rois >= 0 so fx >= 0

    // ---- per-box x setup: select-free 3-tap window weights (registers) ----
    float Wa[POOLN], Wb[POOLN], Wc[POOLN];
#pragma unroll
    for (int j = 0; j < POOLN; j++) {
        float xs = fx + (float)j * sx;
        float xf = floorf(xs);
        float l = xs - xf;
        int ax = (int)xf;
        bool c = (ax - x_lo) > BASE_X[j];  // sample sits one column right
        float m = (xs <= 27.0f) ? 1.0f : 0.0f;
        float u0 = m * (1.0f - l);
        float u1 = m * l;
        Wa[j] = c ? 0.0f : u0;
        Wb[j] = c ? u0   : u1;
        Wc[j] = c ? u1   : 0.0f;
    }

    int colofs[6];
#pragma unroll
    for (int k = 0; k < 6; k++)
        colofs[k] = min(x_lo + k, IMG_W - 1) * C4;

    const float4* base_img = img4 + tid;
    float4* outp = out4 + (size_t)box * (POOLN * POOLN) * C4 + tid;

    // ---- raw 2-row patch cache ----
    float4 pT[6], pB[6];
    int ct;
    {
        int ya0 = (int)floorf(fy);
        ct = min(ya0, IMG_H - 1);
        int cb = min(ya0 + 1, IMG_H - 1);
        LOADROW(ct, pT);
        if (cb != ct) {
            LOADROW(cb, pB);
        } else {
#pragma unroll
            for (int k = 0; k < 6; k++) pB[k] = pT[k];
        }
    }

#pragma unroll
    for (int i = 0; i < POOLN; i++) {
        float ys = fy + (float)i * sy;
        float yf = floorf(ys);
        float ly = ys - yf;
        int ya = (int)yf;
        int t = min(ya, IMG_H - 1);
        int b = min(ya + 1, IMG_H - 1);
        float my = (ys <= 27.0f) ? 1.0f : 0.0f;
        float wA = (1.0f - ly) * my;
        float wB = ly * my;

        if (i > 0 && t != ct) {
            // advance by exactly one image row: new top == old bottom
#pragma unroll
            for (int k = 0; k < 6; k++) pT[k] = pB[k];
            if (b != t) {
                LOADROW(b, pB);
            } else {
#pragma unroll
                for (int k = 0; k < 6; k++) pB[k] = pT[k];
            }
            ct = t;
        }

        // 7 fused 6-tap outputs directly on the raw patch
#pragma unroll
        for (int j = 0; j < POOLN; j++) {
            const int bx = BASE_X[j];
            float ta = wA * Wa[j], ba = wB * Wa[j];
            float tb = wA * Wb[j], bbw = wB * Wb[j];
            float tc = wA * Wc[j], bc = wB * Wc[j];
            float4 v;
            v.x = pT[bx].x * ta + pB[bx].x * ba
                + pT[bx+1].x * tb + pB[bx+1].x * bbw
                + pT[bx+2].x * tc + pB[bx+2].x * bc;
            v.y = pT[bx].y * ta + pB[bx].y * ba
                + pT[bx+1].y * tb + pB[bx+1].y * bbw
                + pT[bx+2].y * tc + pB[bx+2].y * bc;
            v.z = pT[bx].z * ta + pB[bx].z * ba
                + pT[bx+1].z * tb + pB[bx+1].z * bbw
                + pT[bx+2].z * tc + pB[bx+2].z * bc;
            v.w = pT[bx].w * ta + pB[bx].w * ba
                + pT[bx+1].w * tb + pB[bx+1].w * bbw
                + pT[bx+2].w * tc + pB[bx+2].w * bc;
            __stcs(outp + (i * POOLN + j) * C4, v);
        }
    }
}

extern "C" void kernel_launch(void* const* d_in, const int* in_sizes, int n_in,
                              void* d_out, int out_size) {
    const float* img  = (const float*)d_in[0];
    const float* rois = (const float*)d_in[1];
    float* out = (float*)d_out;
    (void)in_sizes; (void)n_in; (void)out_size;
    roi_pool_kernel<<<NBOX, 128>>>((const float4*)img, rois, (float4*)out);
}

// round 17
// speedup vs baseline: 1.0073x; 1.0073x over previous
#include <cuda_runtime.h>

// RoiPooling: crop_and_resize(img[0], 2048 boxes, crop=7) over 512 channels.
// CTA = box, 128 threads. STRIDED channel mapping: thread t owns channels
// {t, t+128, t+256, t+384}. Every load/store is a b32 op where one warp
// covers exactly one 128B line -> 1 wavefront per warp-instruction, draining
// at the fast cross-instruction L1tex rate (1.0 cyc/wf) instead of the
// within-instruction replay rate (2.07 cyc/wf) that LDG.128/STG.128 pay.
// Same raw 2-row patch register cache + select-free fused 6-tap outputs.

#define IMG_H 28
#define IMG_W 28
#define NCH   512
#define POOLN 7
#define NBOX  2048
#define ROWSTRIDE (IMG_W * NCH)   // floats per image row

// Load one clamped image row's 6 patch columns x 4 channel-chunks (24
// independent LDG.32, each 1 line/warp).
#define LOADROW(rowc, dst) do {                                               \
    const float* rp_ = base_img + (rowc) * ROWSTRIDE;                         \
    _Pragma("unroll")                                                         \
    for (int k_ = 0; k_ < 6; k_++) {                                          \
        _Pragma("unroll")                                                     \
        for (int q_ = 0; q_ < 4; q_++)                                        \
            (dst)[k_ * 4 + q_] = __ldg(rp_ + colofs[k_] + q_ * 128);          \
    }                                                                         \
} while (0)

__global__ __launch_bounds__(128, 4) void roi_pool_kernel(
    const float* __restrict__ img,     // img[0]: (28*28, 512)
    const float* __restrict__ rois,
    float* __restrict__ out)
{
    // floor(j * 27*4/(28*6)) for j=0..6; j*sx stays >=0.07 from any integer,
    // far beyond f32 rounding wiggle, so ax[j]-ax[0] ∈ {BASE, BASE+1}.
    const int BASE_X[POOLN] = {0, 0, 1, 1, 2, 3, 3};

    const int box = blockIdx.x;
    const int tid = threadIdx.x;           // channel (mod 128): 0..127

    const float x1 = rois[box * 5 + 3];
    const float y1 = rois[box * 5 + 4];
    const float win = (float)(4.0 / 28.0);
    // Match JAX numerics: ((x1+win)-x1)*27/6 in f32
    const float sx = (((x1 + win) - x1) * 27.0f) / 6.0f;
    const float sy = (((y1 + win) - y1) * 27.0f) / 6.0f;
    const float fx = x1 * 27.0f;
    const float fy = y1 * 27.0f;

    const int x_lo = (int)floorf(fx);      // rois >= 0 so fx >= 0

    // ---- per-box x setup: select-free 3-tap window weights ----
    float Wa[POOLN], Wb[POOLN], Wc[POOLN];
#pragma unroll
    for (int j = 0; j < POOLN; j++) {
        float xs = fx + (float)j * sx;
        float xf = floorf(xs);
        float l = xs - xf;
        int ax = (int)xf;
        bool c = (ax - x_lo) > BASE_X[j];  // sample sits one column right
        float m = (xs <= 27.0f) ? 1.0f : 0.0f;
        float u0 = m * (1.0f - l);
        float u1 = m * l;
        Wa[j] = c ? 0.0f : u0;
        Wb[j] = c ? u0   : u1;
        Wc[j] = c ? u1   : 0.0f;
    }

    int colofs[6];
#pragma unroll
    for (int k = 0; k < 6; k++)
        colofs[k] = min(x_lo + k, IMG_W - 1) * NCH;

    const float* base_img = img + tid;     // channel-offset base
    float* outp = out + (size_t)box * (POOLN * POOLN) * NCH + tid;

    // ---- raw 2-row patch cache: 6 cols x 4 channel-chunks per row ----
    float pT[24], pB[24];
    int ct;
    {
        int ya0 = (int)floorf(fy);
        ct = min(ya0, IMG_H - 1);
        int cb = min(ya0 + 1, IMG_H - 1);
        LOADROW(ct, pT);
        if (cb != ct) {
            LOADROW(cb, pB);
        } else {
#pragma unroll
            for (int k = 0; k < 24; k++) pB[k] = pT[k];
        }
    }

#pragma unroll
    for (int i = 0; i < POOLN; i++) {
        float ys = fy + (float)i * sy;
        float yf = floorf(ys);
        float ly = ys - yf;
        int ya = (int)yf;
        int t = min(ya, IMG_H - 1);
        int b = min(ya + 1, IMG_H - 1);
        float my = (ys <= 27.0f) ? 1.0f : 0.0f;
        float wA = (1.0f - ly) * my;
        float wB = ly * my;

        if (i > 0 && t != ct) {
            // advance by exactly one image row: new top == old bottom
#pragma unroll
            for (int k = 0; k < 24; k++) pT[k] = pB[k];
            if (b != t) {
                LOADROW(b, pB);
            } else {
#pragma unroll
                for (int k = 0; k < 24; k++) pB[k] = pT[k];
            }
            ct = t;
        }

        // 7 fused 6-tap outputs; 4 strided b32 stores each
#pragma unroll
        for (int j = 0; j < POOLN; j++) {
            const int bx = BASE_X[j];
            float ta = wA * Wa[j], ba = wB * Wa[j];
            float tb = wA * Wb[j], bbw = wB * Wb[j];
            float tc = wA * Wc[j], bc = wB * Wc[j];
            float* op = outp + (i * POOLN + j) * NCH;
#pragma unroll
            for (int q = 0; q < 4; q++) {
                float v = pT[bx * 4 + q] * ta + pB[bx * 4 + q] * ba
                        + pT[(bx + 1) * 4 + q] * tb + pB[(bx + 1) * 4 + q] * bbw
                        + pT[(bx + 2) * 4 + q] * tc + pB[(bx + 2) * 4 + q] * bc;
                __stcs(op + q * 128, v);
            }
        }
    }
}

extern "C" void kernel_launch(void* const* d_in, const int* in_sizes, int n_in,
                              void* d_out, int out_size) {
    const float* img  = (const float*)d_in[0];
    const float* rois = (const float*)d_in[1];
    float* out = (float*)d_out;
    (void)in_sizes; (void)n_in; (void)out_size;
    roi_pool_kernel<<<NBOX, 128>>>(img, rois, out);
}